// round 13
// baseline (speedup 1.0000x reference)
#include <cuda_runtime.h>
#include <cstdint>

#define EMB      128
#define NRAD     6
#define NDENSE   3
#define NT       12      // num targets
#define NTP      16      // padded targets in smem
#define MAX_ATOMS 20480
#define MAX_EDGES 660000

#define MLP_ROWS  64     // rows per MLP block
#define MLP_PAIRS 32     // row pairs per block
#define PH        34     // u64 pitch for h tile (even -> LDS.128 aligned)

// -------- persistent device scratch (no allocations allowed) --------
__device__ __align__(16) float g_h[MAX_ATOMS * EMB];
__device__ __align__(16) int   g_row[MAX_ATOMS + 4];
__device__ __align__(16) int   g_cnt[MAX_ATOMS];      // zero-init; re-zeroed each pass
__device__ __align__(16) int   g_cursor[MAX_ATOMS];
__device__ int   g_edges[MAX_EDGES];
__device__ int   g_flag;      // fillscan grid barrier flag (self-resetting)
__device__ int   g_done;      // fillscan arrival counter (self-resetting)
__device__ int   g_ticket;    // gather dynamic work ticket (reset by mlp)

typedef unsigned long long u64;

// -------- packed fp32x2 helpers --------
__device__ __forceinline__ u64 ffma2(u64 a, u64 b, u64 c) {
    u64 d;
    asm("fma.rn.f32x2 %0, %1, %2, %3;" : "=l"(d) : "l"(a), "l"(b), "l"(c));
    return d;
}
__device__ __forceinline__ u64 pack2(float x, float y) {
    u64 r;
    asm("mov.b64 %0, {%1, %2};" : "=l"(r) : "f"(x), "f"(y));
    return r;
}
__device__ __forceinline__ void unpack2(u64 v, float& x, float& y) {
    asm("mov.b64 {%0, %1}, %2;" : "=f"(x), "=f"(y) : "l"(v));
}
__device__ __forceinline__ float silu_f(float x) {
    return __fdividef(x, 1.0f + __expf(-x));
}

// -------- cp.async helpers --------
__device__ __forceinline__ void cp_async16(uint32_t saddr, const void* gptr) {
    asm volatile("cp.async.cg.shared.global [%0], [%1], 16;"
                 :: "r"(saddr), "l"(gptr) : "memory");
}
__device__ __forceinline__ void cp_commit() {
    asm volatile("cp.async.commit_group;" ::: "memory");
}
__device__ __forceinline__ void cp_wait2() {
    asm volatile("cp.async.wait_group 2;" ::: "memory");
}

// -------- inline int64/int32 detection (deterministic) --------
__device__ __forceinline__ bool detect_is64(const void* idnb, int E, int n_atoms,
                                            int* s_flag) {
    if (threadIdx.x < 32) {
        const long long* p = (const long long*)idnb;
        int n = E / 2;
        if (n > 2048) n = 2048;
        int bad = 0;
        for (int i = threadIdx.x; i < n; i += 32) {
            long long v = p[i];
            if (v < 0 || v >= (long long)n_atoms) bad = 1;
        }
        bad = __any_sync(0xffffffffu, bad) ? 1 : 0;
        if (threadIdx.x == 0) *s_flag = bad ? 0 : 1;
    }
    __syncthreads();
    return *s_flag != 0;
}

// ===================================================================
// Kernel 0: histogram of destination atoms.
// ===================================================================
__global__ void hist_kernel(const void* __restrict__ idnb, int E, int n_atoms) {
    __shared__ int s_flag;
    const bool is64 = detect_is64(idnb, E, n_atoms, &s_flag);
    const long long* i64 = (const long long*)idnb;
    const int* i32 = (const int*)idnb;
    for (int e = blockIdx.x * blockDim.x + threadIdx.x; e < E;
         e += gridDim.x * blockDim.x) {
        const int idx = is64 ? (int)i64[e] : i32[e];
        atomicAdd(&g_cnt[idx], 1);
    }
}

// ===================================================================
// Kernel 1: FUSED scan + fill (R11 version, 296 blocks).
// ===================================================================
#define FS_CH 80      // 256 threads x 80 = 20480 >= n_atoms
__global__ void fillscan_kernel(const void* __restrict__ idnb, int E, int n_atoms) {
    __shared__ int s_flag;
    __shared__ int wtot[8];
    const bool is64 = detect_is64(idnb, E, n_atoms, &s_flag);
    const long long* i64 = (const long long*)idnb;
    const int* i32 = (const int*)idnb;
    const int t = threadIdx.x;

    if (blockIdx.x == 0) {
        const int lane = t & 31, wid = t >> 5;
        const int c0 = t * FS_CH;
        int4 vv[FS_CH / 4];
        const int4* cp4 = (const int4*)(g_cnt + c0);
#pragma unroll
        for (int i = 0; i < FS_CH / 4; ++i) vv[i] = cp4[i];
        const int* v = (const int*)vv;

        int sum = 0;
#pragma unroll
        for (int i = 0; i < FS_CH; ++i) sum += v[i];

        int inc = sum;
#pragma unroll
        for (int d = 1; d < 32; d <<= 1) {
            int u = __shfl_up_sync(0xffffffffu, inc, d);
            if (lane >= d) inc += u;
        }
        if (lane == 31) wtot[wid] = inc;
        __syncthreads();
        if (wid == 0 && lane < 8) {
            int u = wtot[lane];
#pragma unroll
            for (int d = 1; d < 8; d <<= 1) {
                int p = __shfl_up_sync(0xffu, u, d);
                if (lane >= d) u += p;
            }
            wtot[lane] = u;
        }
        __syncthreads();

        int run = inc - sum + (wid > 0 ? wtot[wid - 1] : 0);
        int4 ov[FS_CH / 4];
        int* o = (int*)ov;
#pragma unroll
        for (int i = 0; i < FS_CH; ++i) { o[i] = run; run += v[i]; }

        int4* r4 = (int4*)(g_row + c0);
        int4* u4 = (int4*)(g_cursor + c0);
#pragma unroll
        for (int i = 0; i < FS_CH / 4; ++i) { r4[i] = ov[i]; u4[i] = ov[i]; }

        __syncthreads();
        if (t == 0) {
            __threadfence();
            atomicExch(&g_flag, 1);
        }
    } else {
        if (t == 0) {
            while (atomicAdd(&g_flag, 0) == 0) __nanosleep(64);
        }
        __syncthreads();
    }

    const int g0 = blockIdx.x * blockDim.x + t;
    const int gs = gridDim.x * blockDim.x;
    for (int i = g0; i < n_atoms; i += gs) g_cnt[i] = 0;
    for (int e = g0; e < E; e += gs) {
        const int idx = is64 ? (int)i64[e] : i32[e];
        const int pos = atomicAdd(&g_cursor[idx], 1);
        g_edges[pos] = e;
    }

    __syncthreads();
    if (t == 0) {
        const int d = atomicAdd(&g_done, 1);
        if (d == (int)gridDim.x - 1) {
            g_done = 0;
            g_flag = 0;
            __threadfence();
        }
    }
}

// ===================================================================
// Kernel 2: gather + gate, cp.async staged, dynamic atom tickets.
// ===================================================================
#define GS 3
#define GE 4

__global__ __launch_bounds__(256, 4)
void gather_kernel(const float* __restrict__ x,
                   const float* __restrict__ rbf,
                   const float* __restrict__ Wrbf,
                   int n_atoms) {
    __shared__ float4 sx[8][GS * GE][32];
    const int wl   = threadIdx.x >> 5;
    const int lane = threadIdx.x & 31;
    const unsigned FULL = 0xffffffffu;

    const uint32_t sbase =
        (uint32_t)__cvta_generic_to_shared(&sx[wl][0][lane]);

    float4 w[NRAD];
    const float4* w4 = (const float4*)Wrbf;
#pragma unroll
    for (int r = 0; r < NRAD; ++r) w[r] = w4[r * 32 + lane];

    const float4* x4 = (const float4*)x;

    for (;;) {
        int a;
        if (lane == 0) a = atomicAdd(&g_ticket, 1);
        a = __shfl_sync(FULL, a, 0);
        if (a >= n_atoms) break;

        const int s  = __ldg(&g_row[a]);
        const int e1 = __ldg(&g_row[a + 1]);
        float a0 = 0.f, a1 = 0.f, a2 = 0.f, a3 = 0.f;

        for (int base = s; base < e1; base += 32) {
            const int n = min(32, e1 - base);
            const int eid = __ldg(&g_edges[base + min(lane, n - 1)]);

            const float* rp = rbf + (size_t)eid * NRAD;
            const float rb0 = __ldcs(rp + 0), rb1 = __ldcs(rp + 1);
            const float rb2 = __ldcs(rp + 2), rb3 = __ldcs(rp + 3);
            const float rb4 = __ldcs(rp + 4), rb5 = __ldcs(rp + 5);

            const int ng = (n + 3) >> 2;

#pragma unroll
            for (int g = 0; g < GS; ++g) {
                if (g < ng) {
#pragma unroll
                    for (int u = 0; u < GE; ++u) {
                        const int jj = min(g * GE + u, n - 1);
                        const int e = __shfl_sync(FULL, eid, jj);
                        cp_async16(sbase + (uint32_t)(g * GE + u) * 512u,
                                   x4 + (size_t)e * 32 + lane);
                    }
                }
                cp_commit();
            }

            for (int g = 0; g < ng; ++g) {
                cp_wait2();
                const int slot0 = (g % GS) * GE;
#pragma unroll
                for (int u = 0; u < GE; ++u) {
                    const int je = g * GE + u;
                    const int jj = min(je, n - 1);
                    const float m = (je < n) ? 1.f : 0.f;
                    const float r0 = __shfl_sync(FULL, rb0, jj);
                    const float r1 = __shfl_sync(FULL, rb1, jj);
                    const float r2 = __shfl_sync(FULL, rb2, jj);
                    const float r3 = __shfl_sync(FULL, rb3, jj);
                    const float r4 = __shfl_sync(FULL, rb4, jj);
                    const float r5 = __shfl_sync(FULL, rb5, jj);

                    const float4 xv = sx[wl][slot0 + u][lane];

                    float g0 = fmaf(r0, w[0].x, fmaf(r1, w[1].x, fmaf(r2, w[2].x,
                               fmaf(r3, w[3].x, fmaf(r4, w[4].x, r5 * w[5].x)))));
                    float g1 = fmaf(r0, w[0].y, fmaf(r1, w[1].y, fmaf(r2, w[2].y,
                               fmaf(r3, w[3].y, fmaf(r4, w[4].y, r5 * w[5].y)))));
                    float g2 = fmaf(r0, w[0].z, fmaf(r1, w[1].z, fmaf(r2, w[2].z,
                               fmaf(r3, w[3].z, fmaf(r4, w[4].z, r5 * w[5].z)))));
                    float g3 = fmaf(r0, w[0].w, fmaf(r1, w[1].w, fmaf(r2, w[2].w,
                               fmaf(r3, w[3].w, fmaf(r4, w[4].w, r5 * w[5].w)))));

                    a0 = fmaf(m * g0, xv.x, a0);
                    a1 = fmaf(m * g1, xv.y, a1);
                    a2 = fmaf(m * g2, xv.z, a2);
                    a3 = fmaf(m * g3, xv.w, a3);
                }
                const int gi = g + GS;
                if (gi < ng) {
#pragma unroll
                    for (int u = 0; u < GE; ++u) {
                        const int jj = min(gi * GE + u, n - 1);
                        const int e = __shfl_sync(FULL, eid, jj);
                        cp_async16(sbase + (uint32_t)((gi % GS) * GE + u) * 512u,
                                   x4 + (size_t)e * 32 + lane);
                    }
                }
                cp_commit();
            }
        }
        ((float4*)(g_h + (size_t)a * EMB))[lane] = make_float4(a0, a1, a2, a3);
    }
}

// ===================================================================
// Kernel 3 (PROFILED SLOT): fused MLP head — 512 threads, 64 rows,
// 2 blocks/SM -> 32 warps/SM (2x R11). Each warp owns exactly 2
// row-pairs (even base -> one broadcast LDS.128 per k) x 4 cols/lane.
// acc = 16 regs -> fits 64-reg budget of (512,2). Resets g_ticket.
// ===================================================================
#define HS_BYTES   (EMB * PH * 8)          // 34816
#define WS_OFF     HS_BYTES
#define WS_BYTES   (EMB * EMB * 4)         // 65536
#define WFS_OFF    (WS_OFF + WS_BYTES)     // 100352
#define WFS_BYTES  (EMB * NTP * 4)         // 8192
#define BS_OFF     (WFS_OFF + WFS_BYTES)   // 108544
#define BS_BYTES   (EMB * 4)               // 512
#define SMEM_TOTAL (BS_OFF + BS_BYTES)     // 109056  (x2 = 218112/SM)

__global__ __launch_bounds__(512, 2)
void mlp_kernel(const float* __restrict__ dW, const float* __restrict__ dB,
                const float* __restrict__ Wf, float* __restrict__ out,
                int n_atoms) {
    extern __shared__ char smem[];
    u64*   hsu = (u64*)smem;                 // [col][pair], pitch PH=34
    float* hsf = (float*)smem;               // float view, pitch 68
    float* Ws  = (float*)(smem + WS_OFF);
    float* Wfs = (float*)(smem + WFS_OFF);
    float* bss = (float*)(smem + BS_OFF);

    const int t = threadIdx.x;
    const int lane = t & 31, wid = t >> 5;   // wid 0..15
    const int rowbase = blockIdx.x * MLP_ROWS;

    if (blockIdx.x == 0 && t == 0) g_ticket = 0;   // reset for next replay

    // ---- load h tile (transpose into [col][row]) ----
    for (int idx = t; idx < MLP_ROWS * EMB; idx += 512) {
        const int rr = idx >> 7, cc = idx & 127;
        const int gr = rowbase + rr;
        const float v = (gr < n_atoms) ? g_h[(size_t)gr * EMB + cc] : 0.f;
        hsf[cc * (2 * PH) + rr] = v;
    }
    if (t < EMB) {
#pragma unroll
        for (int c = 0; c < NT; ++c) Wfs[t * NTP + c] = Wf[t * NT + c];
    }

    const int j0 = lane * 4;                 // 4 output cols per lane
    const int p0 = wid * 2;                  // 2 pairs per warp (even base)

    // ---- dense layers ----
    for (int li = 0; li < NDENSE; ++li) {
        const float* W = dW + (size_t)li * EMB * EMB;
        {
            const float4* Wg = (const float4*)W;
            float4* Wd = (float4*)Ws;
            for (int idx = t; idx < EMB * EMB / 4; idx += 512) Wd[idx] = Wg[idx];
        }
        if (t < EMB) bss[t] = dB[li * EMB + t];
        __syncthreads();

        u64 acc[2][4];
#pragma unroll
        for (int p = 0; p < 2; ++p)
#pragma unroll
            for (int q = 0; q < 4; ++q) acc[p][q] = 0ull;

#pragma unroll 2
        for (int k = 0; k < EMB; ++k) {
            const float4 wv = *(const float4*)&Ws[k * EMB + j0];
            const u64 w0 = pack2(wv.x, wv.x);
            const u64 w1 = pack2(wv.y, wv.y);
            const u64 w2 = pack2(wv.z, wv.z);
            const u64 w3 = pack2(wv.w, wv.w);
            const uint4 hvv = *(const uint4*)(hsu + k * PH + p0);  // 2 pairs
            const u64* hq = (const u64*)&hvv;
#pragma unroll
            for (int p = 0; p < 2; ++p) {
                acc[p][0] = ffma2(hq[p], w0, acc[p][0]);
                acc[p][1] = ffma2(hq[p], w1, acc[p][1]);
                acc[p][2] = ffma2(hq[p], w2, acc[p][2]);
                acc[p][3] = ffma2(hq[p], w3, acc[p][3]);
            }
        }

        float b[4];
#pragma unroll
        for (int q = 0; q < 4; ++q) b[q] = bss[j0 + q];

        __syncthreads();   // all hsu reads done -> safe to overwrite

#pragma unroll
        for (int p = 0; p < 2; ++p) {
            const int pr = p0 + p;
#pragma unroll
            for (int q = 0; q < 4; ++q) {
                float lo, hi;
                unpack2(acc[p][q], lo, hi);
                lo = silu_f(lo + b[q]);
                hi = silu_f(hi + b[q]);
                hsu[(j0 + q) * PH + pr] = pack2(lo, hi);
            }
        }
        __syncthreads();
    }

    // ---- final projection: [64,128] @ [128,12] -> out ----
    const int c = t & 15;
    const int grp = t >> 4;      // 0..31 = pair index
    if (c < NT) {
        u64 acc = 0ull;
#pragma unroll 4
        for (int k = 0; k < EMB; ++k) {
            const float wfv = Wfs[k * NTP + c];
            acc = ffma2(hsu[k * PH + grp], pack2(wfv, wfv), acc);
        }
        float lo, hi;
        unpack2(acc, lo, hi);
        const int r0 = rowbase + 2 * grp;
        if (r0 < n_atoms)     out[(size_t)r0 * NT + c]       = lo;
        if (r0 + 1 < n_atoms) out[(size_t)(r0 + 1) * NT + c] = hi;
    }
}

// ===================================================================
extern "C" void kernel_launch(void* const* d_in, const int* in_sizes, int n_in,
                              void* d_out, int out_size) {
    const float* x    = (const float*)d_in[0];
    const float* rbf  = (const float*)d_in[1];
    const void*  idnb =               d_in[2];
    const float* Wrbf = (const float*)d_in[4];
    const float* dW   = (const float*)d_in[5];
    const float* dB   = (const float*)d_in[6];
    const float* Wf   = (const float*)d_in[7];
    float* out = (float*)d_out;

    const int E = in_sizes[0] / EMB;
    const int n_atoms = out_size / NT;

    hist_kernel<<<296, 256>>>(idnb, E, n_atoms);            // 0
    fillscan_kernel<<<296, 256>>>(idnb, E, n_atoms);        // 1
    gather_kernel<<<592, 256>>>(x, rbf, Wrbf, n_atoms);     // 2

    cudaFuncSetAttribute(mlp_kernel, cudaFuncAttributeMaxDynamicSharedMemorySize,
                         SMEM_TOTAL);
    const int blocks = (n_atoms + MLP_ROWS - 1) / MLP_ROWS;
    mlp_kernel<<<blocks, 512, SMEM_TOTAL>>>(dW, dB, Wf, out, n_atoms);  // 3 (PROFILED)
}

// round 14
// speedup vs baseline: 1.3162x; 1.3162x over previous
#include <cuda_runtime.h>
#include <cstdint>

#define EMB      128
#define NRAD     6
#define NDENSE   3
#define NT       12      // num targets
#define NTP      16      // padded targets in smem
#define MAX_ATOMS 20480
#define BCAP     128     // bucket capacity per atom (P(overflow) ~ e^-41)

#define MLP_ROWS  68     // rows per MLP block (2 blocks/SM)
#define MLP_PAIRS 34     // row pairs per block
#define PH        36     // u64 pitch for h tile (even -> LDS.128 aligned)

// -------- persistent device scratch (no allocations allowed) --------
__device__ __align__(16) float g_h[MAX_ATOMS * EMB];
__device__ __align__(16) int   g_cnt[MAX_ATOMS];          // zero-init; re-zeroed by mlp
__device__ __align__(16) int   g_edges[MAX_ATOMS * BCAP]; // padded buckets (10.5 MB)
__device__ int   g_ticket;    // gather dynamic work ticket (reset by mlp)

typedef unsigned long long u64;

// -------- packed fp32x2 helpers --------
__device__ __forceinline__ u64 ffma2(u64 a, u64 b, u64 c) {
    u64 d;
    asm("fma.rn.f32x2 %0, %1, %2, %3;" : "=l"(d) : "l"(a), "l"(b), "l"(c));
    return d;
}
__device__ __forceinline__ u64 pack2(float x, float y) {
    u64 r;
    asm("mov.b64 %0, {%1, %2};" : "=l"(r) : "f"(x), "f"(y));
    return r;
}
__device__ __forceinline__ void unpack2(u64 v, float& x, float& y) {
    asm("mov.b64 {%0, %1}, %2;" : "=f"(x), "=f"(y) : "l"(v));
}
__device__ __forceinline__ float silu_f(float x) {
    return __fdividef(x, 1.0f + __expf(-x));
}

// -------- cp.async helpers --------
__device__ __forceinline__ void cp_async16(uint32_t saddr, const void* gptr) {
    asm volatile("cp.async.cg.shared.global [%0], [%1], 16;"
                 :: "r"(saddr), "l"(gptr) : "memory");
}
__device__ __forceinline__ void cp_commit() {
    asm volatile("cp.async.commit_group;" ::: "memory");
}
__device__ __forceinline__ void cp_wait2() {
    asm volatile("cp.async.wait_group 2;" ::: "memory");
}

// -------- inline int64/int32 detection (deterministic) --------
__device__ __forceinline__ bool detect_is64(const void* idnb, int E, int n_atoms,
                                            int* s_flag) {
    if (threadIdx.x < 32) {
        const long long* p = (const long long*)idnb;
        int n = E / 2;
        if (n > 2048) n = 2048;
        int bad = 0;
        for (int i = threadIdx.x; i < n; i += 32) {
            long long v = p[i];
            if (v < 0 || v >= (long long)n_atoms) bad = 1;
        }
        bad = __any_sync(0xffffffffu, bad) ? 1 : 0;
        if (threadIdx.x == 0) *s_flag = bad ? 0 : 1;
    }
    __syncthreads();
    return *s_flag != 0;
}

// ===================================================================
// Kernel 0: single-pass padded-bucket CSR. Replaces hist+scan+fill.
// g_cnt is pre-zeroed (static init on first call; mlp re-zeroes it
// every pass). pos clamp keeps arbitrary inputs memory-safe.
// ===================================================================
__global__ void bucket_kernel(const void* __restrict__ idnb, int E, int n_atoms) {
    __shared__ int s_flag;
    const bool is64 = detect_is64(idnb, E, n_atoms, &s_flag);
    const long long* i64 = (const long long*)idnb;
    const int* i32 = (const int*)idnb;
    for (int e = blockIdx.x * blockDim.x + threadIdx.x; e < E;
         e += gridDim.x * blockDim.x) {
        const int idx = is64 ? (int)i64[e] : i32[e];
        const int pos = atomicAdd(&g_cnt[idx], 1);
        if (pos < BCAP)
            g_edges[((size_t)idx << 7) + pos] = e;
    }
}

// ===================================================================
// Kernel 1: gather + gate, cp.async staged, dynamic atom tickets.
// Reads bucket counts + fixed-stride bucket bases (no row offsets).
// ===================================================================
#define GS 3
#define GE 4

__global__ __launch_bounds__(256, 4)
void gather_kernel(const float* __restrict__ x,
                   const float* __restrict__ rbf,
                   const float* __restrict__ Wrbf,
                   int n_atoms) {
    __shared__ float4 sx[8][GS * GE][32];
    const int wl   = threadIdx.x >> 5;
    const int lane = threadIdx.x & 31;
    const unsigned FULL = 0xffffffffu;

    const uint32_t sbase =
        (uint32_t)__cvta_generic_to_shared(&sx[wl][0][lane]);

    float4 w[NRAD];
    const float4* w4 = (const float4*)Wrbf;
#pragma unroll
    for (int r = 0; r < NRAD; ++r) w[r] = w4[r * 32 + lane];

    const float4* x4 = (const float4*)x;

    for (;;) {
        int a;
        if (lane == 0) a = atomicAdd(&g_ticket, 1);
        a = __shfl_sync(FULL, a, 0);
        if (a >= n_atoms) break;

        const int cnt = min(__ldg(&g_cnt[a]), BCAP);
        const int* bucket = g_edges + ((size_t)a << 7);
        float a0 = 0.f, a1 = 0.f, a2 = 0.f, a3 = 0.f;

        for (int base = 0; base < cnt; base += 32) {
            const int n = min(32, cnt - base);
            const int eid = __ldg(&bucket[base + min(lane, n - 1)]);

            const float* rp = rbf + (size_t)eid * NRAD;
            const float rb0 = __ldcs(rp + 0), rb1 = __ldcs(rp + 1);
            const float rb2 = __ldcs(rp + 2), rb3 = __ldcs(rp + 3);
            const float rb4 = __ldcs(rp + 4), rb5 = __ldcs(rp + 5);

            const int ng = (n + 3) >> 2;

#pragma unroll
            for (int g = 0; g < GS; ++g) {
                if (g < ng) {
#pragma unroll
                    for (int u = 0; u < GE; ++u) {
                        const int jj = min(g * GE + u, n - 1);
                        const int e = __shfl_sync(FULL, eid, jj);
                        cp_async16(sbase + (uint32_t)(g * GE + u) * 512u,
                                   x4 + (size_t)e * 32 + lane);
                    }
                }
                cp_commit();
            }

            for (int g = 0; g < ng; ++g) {
                cp_wait2();
                const int slot0 = (g % GS) * GE;
#pragma unroll
                for (int u = 0; u < GE; ++u) {
                    const int je = g * GE + u;
                    const int jj = min(je, n - 1);
                    const float m = (je < n) ? 1.f : 0.f;
                    const float r0 = __shfl_sync(FULL, rb0, jj);
                    const float r1 = __shfl_sync(FULL, rb1, jj);
                    const float r2 = __shfl_sync(FULL, rb2, jj);
                    const float r3 = __shfl_sync(FULL, rb3, jj);
                    const float r4 = __shfl_sync(FULL, rb4, jj);
                    const float r5 = __shfl_sync(FULL, rb5, jj);

                    const float4 xv = sx[wl][slot0 + u][lane];

                    float g0 = fmaf(r0, w[0].x, fmaf(r1, w[1].x, fmaf(r2, w[2].x,
                               fmaf(r3, w[3].x, fmaf(r4, w[4].x, r5 * w[5].x)))));
                    float g1 = fmaf(r0, w[0].y, fmaf(r1, w[1].y, fmaf(r2, w[2].y,
                               fmaf(r3, w[3].y, fmaf(r4, w[4].y, r5 * w[5].y)))));
                    float g2 = fmaf(r0, w[0].z, fmaf(r1, w[1].z, fmaf(r2, w[2].z,
                               fmaf(r3, w[3].z, fmaf(r4, w[4].z, r5 * w[5].z)))));
                    float g3 = fmaf(r0, w[0].w, fmaf(r1, w[1].w, fmaf(r2, w[2].w,
                               fmaf(r3, w[3].w, fmaf(r4, w[4].w, r5 * w[5].w)))));

                    a0 = fmaf(m * g0, xv.x, a0);
                    a1 = fmaf(m * g1, xv.y, a1);
                    a2 = fmaf(m * g2, xv.z, a2);
                    a3 = fmaf(m * g3, xv.w, a3);
                }
                const int gi = g + GS;
                if (gi < ng) {
#pragma unroll
                    for (int u = 0; u < GE; ++u) {
                        const int jj = min(gi * GE + u, n - 1);
                        const int e = __shfl_sync(FULL, eid, jj);
                        cp_async16(sbase + (uint32_t)((gi % GS) * GE + u) * 512u,
                                   x4 + (size_t)e * 32 + lane);
                    }
                }
                cp_commit();
            }
        }
        ((float4*)(g_h + (size_t)a * EMB))[lane] = make_float4(a0, a1, a2, a3);
    }
}

// ===================================================================
// Kernel 2 (PROFILED SLOT): fused MLP head — the R11 champion config
// (68 rows, 256 thr, 2 blocks/SM, 4 pairs + extra pair per warp).
// Prologue zeroes g_cnt + resets g_ticket for the next graph replay.
// ===================================================================
#define HS_BYTES   (EMB * PH * 8)          // 36864
#define WS_OFF     HS_BYTES
#define WS_BYTES   (EMB * EMB * 4)         // 65536
#define WFS_OFF    (WS_OFF + WS_BYTES)     // 102400
#define WFS_BYTES  (EMB * NTP * 4)         // 8192
#define BS_OFF     (WFS_OFF + WFS_BYTES)   // 110592
#define BS_BYTES   (EMB * 4)               // 512
#define SMEM_TOTAL (BS_OFF + BS_BYTES)     // 111104  (x2 = 222208/SM)

__global__ __launch_bounds__(256, 2)
void mlp_kernel(const float* __restrict__ dW, const float* __restrict__ dB,
                const float* __restrict__ Wf, float* __restrict__ out,
                int n_atoms) {
    extern __shared__ char smem[];
    u64*   hsu = (u64*)smem;                 // [col][pair], pitch PH=36
    float* hsf = (float*)smem;               // float view, pitch 72
    float* Ws  = (float*)(smem + WS_OFF);
    float* Wfs = (float*)(smem + WFS_OFF);
    float* bss = (float*)(smem + BS_OFF);

    const int t = threadIdx.x;
    const int lane = t & 31, wid = t >> 5;
    const int rowbase = blockIdx.x * MLP_ROWS;

    // ---- reset scratch for the NEXT graph replay (after gather read it)
    {
        const int i = blockIdx.x * 256 + t;      // grid*256 >= 75520 > n_atoms
        if (i < n_atoms) g_cnt[i] = 0;
        if (i == 0) g_ticket = 0;
    }

    // ---- load h tile (coalesced global, transpose into [col][row]) ----
    for (int idx = t; idx < MLP_ROWS * EMB; idx += 256) {
        const int rr = idx >> 7, cc = idx & 127;
        const int gr = rowbase + rr;
        const float v = (gr < n_atoms) ? g_h[(size_t)gr * EMB + cc] : 0.f;
        hsf[cc * (2 * PH) + rr] = v;
    }
    if (t < EMB) {
#pragma unroll
        for (int c = 0; c < NT; ++c) Wfs[t * NTP + c] = Wf[t * NT + c];
    }

    const int j0 = lane * 4;                 // 4 output cols per lane
    const int p0 = wid * 4;                  // pair base (0..28)
    const bool has_x = (wid < 2);            // extra pair 32+wid
    const int px = 32 + wid;

    // ---- dense layers ----
    for (int li = 0; li < NDENSE; ++li) {
        const float* W = dW + (size_t)li * EMB * EMB;
        {
            const float4* Wg = (const float4*)W;
            float4* Wd = (float4*)Ws;
            for (int idx = t; idx < EMB * EMB / 4; idx += 256) Wd[idx] = Wg[idx];
        }
        if (t < EMB) bss[t] = dB[li * EMB + t];
        __syncthreads();

        u64 acc[4][4], accx[4];
#pragma unroll
        for (int p = 0; p < 4; ++p)
#pragma unroll
            for (int q = 0; q < 4; ++q) acc[p][q] = 0ull;
#pragma unroll
        for (int q = 0; q < 4; ++q) accx[q] = 0ull;

#pragma unroll 2
        for (int k = 0; k < EMB; ++k) {
            const float4 wv = *(const float4*)&Ws[k * EMB + j0];
            const u64 w0 = pack2(wv.x, wv.x);
            const u64 w1 = pack2(wv.y, wv.y);
            const u64 w2 = pack2(wv.z, wv.z);
            const u64 w3 = pack2(wv.w, wv.w);
            const u64* hrow = hsu + k * PH;
            const uint4* hp = (const uint4*)(hrow + p0);
            uint4 hvv[2];
            hvv[0] = hp[0];
            hvv[1] = hp[1];
            const u64* hq = (const u64*)hvv;
#pragma unroll
            for (int p = 0; p < 4; ++p) {
                acc[p][0] = ffma2(hq[p], w0, acc[p][0]);
                acc[p][1] = ffma2(hq[p], w1, acc[p][1]);
                acc[p][2] = ffma2(hq[p], w2, acc[p][2]);
                acc[p][3] = ffma2(hq[p], w3, acc[p][3]);
            }
            if (has_x) {                     // warp-uniform branch
                const u64 hx = hrow[px];
                accx[0] = ffma2(hx, w0, accx[0]);
                accx[1] = ffma2(hx, w1, accx[1]);
                accx[2] = ffma2(hx, w2, accx[2]);
                accx[3] = ffma2(hx, w3, accx[3]);
            }
        }

        float b[4];
#pragma unroll
        for (int q = 0; q < 4; ++q) b[q] = bss[j0 + q];

        __syncthreads();   // all hsu reads done -> safe to overwrite

#pragma unroll
        for (int p = 0; p < 4; ++p) {
            const int pr = p0 + p;
#pragma unroll
            for (int q = 0; q < 4; ++q) {
                float lo, hi;
                unpack2(acc[p][q], lo, hi);
                lo = silu_f(lo + b[q]);
                hi = silu_f(hi + b[q]);
                hsu[(j0 + q) * PH + pr] = pack2(lo, hi);
            }
        }
        if (has_x) {
#pragma unroll
            for (int q = 0; q < 4; ++q) {
                float lo, hi;
                unpack2(accx[q], lo, hi);
                lo = silu_f(lo + b[q]);
                hi = silu_f(hi + b[q]);
                hsu[(j0 + q) * PH + px] = pack2(lo, hi);
            }
        }
        __syncthreads();
    }

    // ---- final projection: [68,128] @ [128,12] -> out ----
    const int c = t & 15;
    const int grp = t >> 4;      // 0..15
    if (c < NT) {
#pragma unroll
        for (int i = 0; i < 3; ++i) {
            const int pr = grp + 16 * i;
            if (pr < MLP_PAIRS) {
                u64 acc = 0ull;
#pragma unroll 4
                for (int k = 0; k < EMB; ++k) {
                    const float wfv = Wfs[k * NTP + c];
                    acc = ffma2(hsu[k * PH + pr], pack2(wfv, wfv), acc);
                }
                float lo, hi;
                unpack2(acc, lo, hi);
                const int r0 = rowbase + 2 * pr;
                if (r0 < n_atoms)     out[(size_t)r0 * NT + c]       = lo;
                if (r0 + 1 < n_atoms) out[(size_t)(r0 + 1) * NT + c] = hi;
            }
        }
    }
}

// ===================================================================
extern "C" void kernel_launch(void* const* d_in, const int* in_sizes, int n_in,
                              void* d_out, int out_size) {
    const float* x    = (const float*)d_in[0];
    const float* rbf  = (const float*)d_in[1];
    const void*  idnb =               d_in[2];
    const float* Wrbf = (const float*)d_in[4];
    const float* dW   = (const float*)d_in[5];
    const float* dB   = (const float*)d_in[6];
    const float* Wf   = (const float*)d_in[7];
    float* out = (float*)d_out;

    const int E = in_sizes[0] / EMB;
    const int n_atoms = out_size / NT;

    bucket_kernel<<<296, 256>>>(idnb, E, n_atoms);          // 0 (single-pass CSR)
    gather_kernel<<<592, 256>>>(x, rbf, Wrbf, n_atoms);     // 1

    cudaFuncSetAttribute(mlp_kernel, cudaFuncAttributeMaxDynamicSharedMemorySize,
                         SMEM_TOTAL);
    const int blocks = (n_atoms + MLP_ROWS - 1) / MLP_ROWS;
    mlp_kernel<<<blocks, 256, SMEM_TOTAL>>>(dW, dB, Wf, out, n_atoms);  // 2 (PROFILED on replay)
}

// round 15
// speedup vs baseline: 1.3259x; 1.0074x over previous
#include <cuda_runtime.h>
#include <cstdint>

#define EMB      128
#define NRAD     6
#define NDENSE   3
#define NT       12      // num targets
#define NTP      16      // padded targets in smem
#define MAX_ATOMS 20480
#define BCAP     128     // bucket capacity per atom (P(overflow) ~ e^-41)

#define MLP_ROWS  68     // rows per MLP block (2 blocks/SM)
#define MLP_PAIRS 34     // row pairs per block
#define PH        36     // u64 pitch for h tile (even -> LDS.128 aligned)

// -------- persistent device scratch (no allocations allowed) --------
__device__ __align__(16) float g_h[MAX_ATOMS * EMB];
__device__ __align__(16) int   g_cnt[MAX_ATOMS];          // zero-init; re-zeroed by mlp
__device__ __align__(16) int   g_edges[MAX_ATOMS * BCAP]; // padded buckets (10.5 MB)
__device__ int   g_ticket;    // gather dynamic work ticket (reset by mlp)

typedef unsigned long long u64;

// -------- packed fp32x2 helpers --------
__device__ __forceinline__ u64 ffma2(u64 a, u64 b, u64 c) {
    u64 d;
    asm("fma.rn.f32x2 %0, %1, %2, %3;" : "=l"(d) : "l"(a), "l"(b), "l"(c));
    return d;
}
__device__ __forceinline__ u64 pack2(float x, float y) {
    u64 r;
    asm("mov.b64 %0, {%1, %2};" : "=l"(r) : "f"(x), "f"(y));
    return r;
}
__device__ __forceinline__ void unpack2(u64 v, float& x, float& y) {
    asm("mov.b64 {%0, %1}, %2;" : "=f"(x), "=f"(y) : "l"(v));
}
__device__ __forceinline__ float silu_f(float x) {
    return __fdividef(x, 1.0f + __expf(-x));
}

// -------- cp.async helpers --------
__device__ __forceinline__ void cp_async16(uint32_t saddr, const void* gptr) {
    asm volatile("cp.async.cg.shared.global [%0], [%1], 16;"
                 :: "r"(saddr), "l"(gptr) : "memory");
}
__device__ __forceinline__ void cp_commit() {
    asm volatile("cp.async.commit_group;" ::: "memory");
}
__device__ __forceinline__ void cp_wait2() {
    asm volatile("cp.async.wait_group 2;" ::: "memory");
}

// -------- inline int64/int32 detection (deterministic) --------
__device__ __forceinline__ bool detect_is64(const void* idnb, int E, int n_atoms,
                                            int* s_flag) {
    if (threadIdx.x < 32) {
        const long long* p = (const long long*)idnb;
        int n = E / 2;
        if (n > 512) n = 512;        // (1/n_atoms)^512 misdetect prob ~ 0
        int bad = 0;
        for (int i = threadIdx.x; i < n; i += 32) {
            long long v = p[i];
            if (v < 0 || v >= (long long)n_atoms) bad = 1;
        }
        bad = __any_sync(0xffffffffu, bad) ? 1 : 0;
        if (threadIdx.x == 0) *s_flag = bad ? 0 : 1;
    }
    __syncthreads();
    return *s_flag != 0;
}

// ===================================================================
// Kernel 0: single-pass padded-bucket CSR, 4-way unrolled so 4
// independent LDG->ATOM->STG chains are in flight per thread
// (R14 profile: issue=3% = one serial chain exposed).
// ===================================================================
__global__ __launch_bounds__(256)
void bucket_kernel(const void* __restrict__ idnb, int E, int n_atoms) {
    __shared__ int s_flag;
    const bool is64 = detect_is64(idnb, E, n_atoms, &s_flag);
    const long long* i64 = (const long long*)idnb;
    const int* i32 = (const int*)idnb;

    const int tid = blockIdx.x * blockDim.x + threadIdx.x;
    const int gs  = gridDim.x * blockDim.x;

    // 4-way unrolled main stretch
    int e = tid * 4;
    const int stride = gs * 4;
    for (; e + 3 < E; e += stride) {
        int idx[4];
#pragma unroll
        for (int u = 0; u < 4; ++u)
            idx[u] = is64 ? (int)i64[e + u] : i32[e + u];
        int pos[4];
#pragma unroll
        for (int u = 0; u < 4; ++u)
            pos[u] = atomicAdd(&g_cnt[idx[u]], 1);
#pragma unroll
        for (int u = 0; u < 4; ++u)
            if (pos[u] < BCAP)
                g_edges[((size_t)idx[u] << 7) + pos[u]] = e + u;
    }
    // tail
    for (; e < E; ++e) {
        const int idx = is64 ? (int)i64[e] : i32[e];
        const int pos = atomicAdd(&g_cnt[idx], 1);
        if (pos < BCAP)
            g_edges[((size_t)idx << 7) + pos] = e;
    }
}

// ===================================================================
// Kernel 1: gather + gate, cp.async staged, dynamic atom tickets.
// ===================================================================
#define GS 3
#define GE 4

__global__ __launch_bounds__(256, 4)
void gather_kernel(const float* __restrict__ x,
                   const float* __restrict__ rbf,
                   const float* __restrict__ Wrbf,
                   int n_atoms) {
    __shared__ float4 sx[8][GS * GE][32];
    const int wl   = threadIdx.x >> 5;
    const int lane = threadIdx.x & 31;
    const unsigned FULL = 0xffffffffu;

    const uint32_t sbase =
        (uint32_t)__cvta_generic_to_shared(&sx[wl][0][lane]);

    float4 w[NRAD];
    const float4* w4 = (const float4*)Wrbf;
#pragma unroll
    for (int r = 0; r < NRAD; ++r) w[r] = w4[r * 32 + lane];

    const float4* x4 = (const float4*)x;

    for (;;) {
        int a;
        if (lane == 0) a = atomicAdd(&g_ticket, 1);
        a = __shfl_sync(FULL, a, 0);
        if (a >= n_atoms) break;

        const int cnt = min(__ldg(&g_cnt[a]), BCAP);
        const int* bucket = g_edges + ((size_t)a << 7);
        float a0 = 0.f, a1 = 0.f, a2 = 0.f, a3 = 0.f;

        for (int base = 0; base < cnt; base += 32) {
            const int n = min(32, cnt - base);
            const int eid = __ldg(&bucket[base + min(lane, n - 1)]);

            const float* rp = rbf + (size_t)eid * NRAD;
            const float rb0 = __ldcs(rp + 0), rb1 = __ldcs(rp + 1);
            const float rb2 = __ldcs(rp + 2), rb3 = __ldcs(rp + 3);
            const float rb4 = __ldcs(rp + 4), rb5 = __ldcs(rp + 5);

            const int ng = (n + 3) >> 2;

#pragma unroll
            for (int g = 0; g < GS; ++g) {
                if (g < ng) {
#pragma unroll
                    for (int u = 0; u < GE; ++u) {
                        const int jj = min(g * GE + u, n - 1);
                        const int e = __shfl_sync(FULL, eid, jj);
                        cp_async16(sbase + (uint32_t)(g * GE + u) * 512u,
                                   x4 + (size_t)e * 32 + lane);
                    }
                }
                cp_commit();
            }

            for (int g = 0; g < ng; ++g) {
                cp_wait2();
                const int slot0 = (g % GS) * GE;
#pragma unroll
                for (int u = 0; u < GE; ++u) {
                    const int je = g * GE + u;
                    const int jj = min(je, n - 1);
                    const float m = (je < n) ? 1.f : 0.f;
                    const float r0 = __shfl_sync(FULL, rb0, jj);
                    const float r1 = __shfl_sync(FULL, rb1, jj);
                    const float r2 = __shfl_sync(FULL, rb2, jj);
                    const float r3 = __shfl_sync(FULL, rb3, jj);
                    const float r4 = __shfl_sync(FULL, rb4, jj);
                    const float r5 = __shfl_sync(FULL, rb5, jj);

                    const float4 xv = sx[wl][slot0 + u][lane];

                    float g0 = fmaf(r0, w[0].x, fmaf(r1, w[1].x, fmaf(r2, w[2].x,
                               fmaf(r3, w[3].x, fmaf(r4, w[4].x, r5 * w[5].x)))));
                    float g1 = fmaf(r0, w[0].y, fmaf(r1, w[1].y, fmaf(r2, w[2].y,
                               fmaf(r3, w[3].y, fmaf(r4, w[4].y, r5 * w[5].y)))));
                    float g2 = fmaf(r0, w[0].z, fmaf(r1, w[1].z, fmaf(r2, w[2].z,
                               fmaf(r3, w[3].z, fmaf(r4, w[4].z, r5 * w[5].z)))));
                    float g3 = fmaf(r0, w[0].w, fmaf(r1, w[1].w, fmaf(r2, w[2].w,
                               fmaf(r3, w[3].w, fmaf(r4, w[4].w, r5 * w[5].w)))));

                    a0 = fmaf(m * g0, xv.x, a0);
                    a1 = fmaf(m * g1, xv.y, a1);
                    a2 = fmaf(m * g2, xv.z, a2);
                    a3 = fmaf(m * g3, xv.w, a3);
                }
                const int gi = g + GS;
                if (gi < ng) {
#pragma unroll
                    for (int u = 0; u < GE; ++u) {
                        const int jj = min(gi * GE + u, n - 1);
                        const int e = __shfl_sync(FULL, eid, jj);
                        cp_async16(sbase + (uint32_t)((gi % GS) * GE + u) * 512u,
                                   x4 + (size_t)e * 32 + lane);
                    }
                }
                cp_commit();
            }
        }
        ((float4*)(g_h + (size_t)a * EMB))[lane] = make_float4(a0, a1, a2, a3);
    }
}

// ===================================================================
// Kernel 2: fused MLP head — R11/R14 champion config (68 rows,
// 256 thr, 2 blocks/SM, 4 pairs + extra pair per warp).
// Prologue zeroes g_cnt + resets g_ticket for the next graph replay.
// ===================================================================
#define HS_BYTES   (EMB * PH * 8)          // 36864
#define WS_OFF     HS_BYTES
#define WS_BYTES   (EMB * EMB * 4)         // 65536
#define WFS_OFF    (WS_OFF + WS_BYTES)     // 102400
#define WFS_BYTES  (EMB * NTP * 4)         // 8192
#define BS_OFF     (WFS_OFF + WFS_BYTES)   // 110592
#define BS_BYTES   (EMB * 4)               // 512
#define SMEM_TOTAL (BS_OFF + BS_BYTES)     // 111104  (x2 = 222208/SM)

__global__ __launch_bounds__(256, 2)
void mlp_kernel(const float* __restrict__ dW, const float* __restrict__ dB,
                const float* __restrict__ Wf, float* __restrict__ out,
                int n_atoms) {
    extern __shared__ char smem[];
    u64*   hsu = (u64*)smem;                 // [col][pair], pitch PH=36
    float* hsf = (float*)smem;               // float view, pitch 72
    float* Ws  = (float*)(smem + WS_OFF);
    float* Wfs = (float*)(smem + WFS_OFF);
    float* bss = (float*)(smem + BS_OFF);

    const int t = threadIdx.x;
    const int lane = t & 31, wid = t >> 5;
    const int rowbase = blockIdx.x * MLP_ROWS;

    // ---- reset scratch for the NEXT graph replay (after gather read it)
    {
        const int i = blockIdx.x * 256 + t;      // grid*256 >= 75520 > n_atoms
        if (i < n_atoms) g_cnt[i] = 0;
        if (i == 0) g_ticket = 0;
    }

    // ---- load h tile (coalesced global, transpose into [col][row]) ----
    for (int idx = t; idx < MLP_ROWS * EMB; idx += 256) {
        const int rr = idx >> 7, cc = idx & 127;
        const int gr = rowbase + rr;
        const float v = (gr < n_atoms) ? g_h[(size_t)gr * EMB + cc] : 0.f;
        hsf[cc * (2 * PH) + rr] = v;
    }
    if (t < EMB) {
#pragma unroll
        for (int c = 0; c < NT; ++c) Wfs[t * NTP + c] = Wf[t * NT + c];
    }

    const int j0 = lane * 4;                 // 4 output cols per lane
    const int p0 = wid * 4;                  // pair base (0..28)
    const bool has_x = (wid < 2);            // extra pair 32+wid
    const int px = 32 + wid;

    // ---- dense layers ----
    for (int li = 0; li < NDENSE; ++li) {
        const float* W = dW + (size_t)li * EMB * EMB;
        {
            const float4* Wg = (const float4*)W;
            float4* Wd = (float4*)Ws;
            for (int idx = t; idx < EMB * EMB / 4; idx += 256) Wd[idx] = Wg[idx];
        }
        if (t < EMB) bss[t] = dB[li * EMB + t];
        __syncthreads();

        u64 acc[4][4], accx[4];
#pragma unroll
        for (int p = 0; p < 4; ++p)
#pragma unroll
            for (int q = 0; q < 4; ++q) acc[p][q] = 0ull;
#pragma unroll
        for (int q = 0; q < 4; ++q) accx[q] = 0ull;

#pragma unroll 2
        for (int k = 0; k < EMB; ++k) {
            const float4 wv = *(const float4*)&Ws[k * EMB + j0];
            const u64 w0 = pack2(wv.x, wv.x);
            const u64 w1 = pack2(wv.y, wv.y);
            const u64 w2 = pack2(wv.z, wv.z);
            const u64 w3 = pack2(wv.w, wv.w);
            const u64* hrow = hsu + k * PH;
            const uint4* hp = (const uint4*)(hrow + p0);
            uint4 hvv[2];
            hvv[0] = hp[0];
            hvv[1] = hp[1];
            const u64* hq = (const u64*)hvv;
#pragma unroll
            for (int p = 0; p < 4; ++p) {
                acc[p][0] = ffma2(hq[p], w0, acc[p][0]);
                acc[p][1] = ffma2(hq[p], w1, acc[p][1]);
                acc[p][2] = ffma2(hq[p], w2, acc[p][2]);
                acc[p][3] = ffma2(hq[p], w3, acc[p][3]);
            }
            if (has_x) {                     // warp-uniform branch
                const u64 hx = hrow[px];
                accx[0] = ffma2(hx, w0, accx[0]);
                accx[1] = ffma2(hx, w1, accx[1]);
                accx[2] = ffma2(hx, w2, accx[2]);
                accx[3] = ffma2(hx, w3, accx[3]);
            }
        }

        float b[4];
#pragma unroll
        for (int q = 0; q < 4; ++q) b[q] = bss[j0 + q];

        __syncthreads();   // all hsu reads done -> safe to overwrite

#pragma unroll
        for (int p = 0; p < 4; ++p) {
            const int pr = p0 + p;
#pragma unroll
            for (int q = 0; q < 4; ++q) {
                float lo, hi;
                unpack2(acc[p][q], lo, hi);
                lo = silu_f(lo + b[q]);
                hi = silu_f(hi + b[q]);
                hsu[(j0 + q) * PH + pr] = pack2(lo, hi);
            }
        }
        if (has_x) {
#pragma unroll
            for (int q = 0; q < 4; ++q) {
                float lo, hi;
                unpack2(accx[q], lo, hi);
                lo = silu_f(lo + b[q]);
                hi = silu_f(hi + b[q]);
                hsu[(j0 + q) * PH + px] = pack2(lo, hi);
            }
        }
        __syncthreads();
    }

    // ---- final projection: [68,128] @ [128,12] -> out ----
    const int c = t & 15;
    const int grp = t >> 4;      // 0..15
    if (c < NT) {
#pragma unroll
        for (int i = 0; i < 3; ++i) {
            const int pr = grp + 16 * i;
            if (pr < MLP_PAIRS) {
                u64 acc = 0ull;
#pragma unroll 4
                for (int k = 0; k < EMB; ++k) {
                    const float wfv = Wfs[k * NTP + c];
                    acc = ffma2(hsu[k * PH + pr], pack2(wfv, wfv), acc);
                }
                float lo, hi;
                unpack2(acc, lo, hi);
                const int r0 = rowbase + 2 * pr;
                if (r0 < n_atoms)     out[(size_t)r0 * NT + c]       = lo;
                if (r0 + 1 < n_atoms) out[(size_t)(r0 + 1) * NT + c] = hi;
            }
        }
    }
}

// ===================================================================
extern "C" void kernel_launch(void* const* d_in, const int* in_sizes, int n_in,
                              void* d_out, int out_size) {
    const float* x    = (const float*)d_in[0];
    const float* rbf  = (const float*)d_in[1];
    const void*  idnb =               d_in[2];
    const float* Wrbf = (const float*)d_in[4];
    const float* dW   = (const float*)d_in[5];
    const float* dB   = (const float*)d_in[6];
    const float* Wf   = (const float*)d_in[7];
    float* out = (float*)d_out;

    const int E = in_sizes[0] / EMB;
    const int n_atoms = out_size / NT;

    bucket_kernel<<<592, 256>>>(idnb, E, n_atoms);          // 0 (unrolled single-pass CSR)
    gather_kernel<<<592, 256>>>(x, rbf, Wrbf, n_atoms);     // 1

    cudaFuncSetAttribute(mlp_kernel, cudaFuncAttributeMaxDynamicSharedMemorySize,
                         SMEM_TOTAL);
    const int blocks = (n_atoms + MLP_ROWS - 1) / MLP_ROWS;
    mlp_kernel<<<blocks, 256, SMEM_TOTAL>>>(dW, dB, Wf, out, n_atoms);  // 2
}

// round 16
// speedup vs baseline: 1.3504x; 1.0185x over previous
#include <cuda_runtime.h>
#include <cstdint>

#define EMB      128
#define NRAD     6
#define NDENSE   3
#define NT       12      // num targets
#define NTP      16      // padded targets in smem
#define MAX_ATOMS 20480
#define BCAP     128     // bucket capacity per atom (P(overflow) ~ e^-41)

#define MLP_ROWS  68     // rows per MLP block (2 blocks/SM)
#define MLP_PAIRS 34     // row pairs per block
#define PH        36     // u64 pitch for h tile (even -> LDS.128 aligned)

// -------- persistent device scratch (no allocations allowed) --------
__device__ __align__(16) float g_h[MAX_ATOMS * EMB];
__device__ __align__(16) int   g_cnt[MAX_ATOMS];          // zero-init; re-zeroed by mlp
__device__ __align__(16) int   g_edges[MAX_ATOMS * BCAP]; // padded buckets (10.5 MB)
__device__ int   g_ticket;    // gather dynamic work ticket (reset by mlp)

typedef unsigned long long u64;

// -------- packed fp32x2 helpers --------
__device__ __forceinline__ u64 ffma2(u64 a, u64 b, u64 c) {
    u64 d;
    asm("fma.rn.f32x2 %0, %1, %2, %3;" : "=l"(d) : "l"(a), "l"(b), "l"(c));
    return d;
}
__device__ __forceinline__ u64 pack2(float x, float y) {
    u64 r;
    asm("mov.b64 %0, {%1, %2};" : "=l"(r) : "f"(x), "f"(y));
    return r;
}
__device__ __forceinline__ void unpack2(u64 v, float& x, float& y) {
    asm("mov.b64 {%0, %1}, %2;" : "=f"(x), "=f"(y) : "l"(v));
}
__device__ __forceinline__ float silu_f(float x) {
    return __fdividef(x, 1.0f + __expf(-x));
}
__device__ __forceinline__ u64 silu2(u64 v, float b) {
    float lo, hi;
    unpack2(v, lo, hi);
    lo = silu_f(lo + b);
    hi = silu_f(hi + b);
    return pack2(lo, hi);
}

// -------- cp.async helpers --------
__device__ __forceinline__ void cp_async16(uint32_t saddr, const void* gptr) {
    asm volatile("cp.async.cg.shared.global [%0], [%1], 16;"
                 :: "r"(saddr), "l"(gptr) : "memory");
}
__device__ __forceinline__ void cp_commit() {
    asm volatile("cp.async.commit_group;" ::: "memory");
}
__device__ __forceinline__ void cp_wait2() {
    asm volatile("cp.async.wait_group 2;" ::: "memory");
}

// -------- inline int64/int32 detection (deterministic) --------
__device__ __forceinline__ bool detect_is64(const void* idnb, int E, int n_atoms,
                                            int* s_flag) {
    if (threadIdx.x < 32) {
        const long long* p = (const long long*)idnb;
        int n = E / 2;
        if (n > 512) n = 512;
        int bad = 0;
        for (int i = threadIdx.x; i < n; i += 32) {
            long long v = p[i];
            if (v < 0 || v >= (long long)n_atoms) bad = 1;
        }
        bad = __any_sync(0xffffffffu, bad) ? 1 : 0;
        if (threadIdx.x == 0) *s_flag = bad ? 0 : 1;
    }
    __syncthreads();
    return *s_flag != 0;
}

// ===================================================================
// Kernel 0: single-pass padded-bucket CSR, 4-way unrolled (frozen).
// ===================================================================
__global__ __launch_bounds__(256)
void bucket_kernel(const void* __restrict__ idnb, int E, int n_atoms) {
    __shared__ int s_flag;
    const bool is64 = detect_is64(idnb, E, n_atoms, &s_flag);
    const long long* i64 = (const long long*)idnb;
    const int* i32 = (const int*)idnb;

    const int tid = blockIdx.x * blockDim.x + threadIdx.x;
    const int gs  = gridDim.x * blockDim.x;

    int e = tid * 4;
    const int stride = gs * 4;
    for (; e + 3 < E; e += stride) {
        int idx[4];
#pragma unroll
        for (int u = 0; u < 4; ++u)
            idx[u] = is64 ? (int)i64[e + u] : i32[e + u];
        int pos[4];
#pragma unroll
        for (int u = 0; u < 4; ++u)
            pos[u] = atomicAdd(&g_cnt[idx[u]], 1);
#pragma unroll
        for (int u = 0; u < 4; ++u)
            if (pos[u] < BCAP)
                g_edges[((size_t)idx[u] << 7) + pos[u]] = e + u;
    }
    for (; e < E; ++e) {
        const int idx = is64 ? (int)i64[e] : i32[e];
        const int pos = atomicAdd(&g_cnt[idx], 1);
        if (pos < BCAP)
            g_edges[((size_t)idx << 7) + pos] = e;
    }
}

// ===================================================================
// Kernel 1: gather + gate, cp.async staged, dynamic tickets (frozen).
// ===================================================================
#define GS 3
#define GE 4

__global__ __launch_bounds__(256, 4)
void gather_kernel(const float* __restrict__ x,
                   const float* __restrict__ rbf,
                   const float* __restrict__ Wrbf,
                   int n_atoms) {
    __shared__ float4 sx[8][GS * GE][32];
    const int wl   = threadIdx.x >> 5;
    const int lane = threadIdx.x & 31;
    const unsigned FULL = 0xffffffffu;

    const uint32_t sbase =
        (uint32_t)__cvta_generic_to_shared(&sx[wl][0][lane]);

    float4 w[NRAD];
    const float4* w4 = (const float4*)Wrbf;
#pragma unroll
    for (int r = 0; r < NRAD; ++r) w[r] = w4[r * 32 + lane];

    const float4* x4 = (const float4*)x;

    for (;;) {
        int a;
        if (lane == 0) a = atomicAdd(&g_ticket, 1);
        a = __shfl_sync(FULL, a, 0);
        if (a >= n_atoms) break;

        const int cnt = min(__ldg(&g_cnt[a]), BCAP);
        const int* bucket = g_edges + ((size_t)a << 7);
        float a0 = 0.f, a1 = 0.f, a2 = 0.f, a3 = 0.f;

        for (int base = 0; base < cnt; base += 32) {
            const int n = min(32, cnt - base);
            const int eid = __ldg(&bucket[base + min(lane, n - 1)]);

            const float* rp = rbf + (size_t)eid * NRAD;
            const float rb0 = __ldcs(rp + 0), rb1 = __ldcs(rp + 1);
            const float rb2 = __ldcs(rp + 2), rb3 = __ldcs(rp + 3);
            const float rb4 = __ldcs(rp + 4), rb5 = __ldcs(rp + 5);

            const int ng = (n + 3) >> 2;

#pragma unroll
            for (int g = 0; g < GS; ++g) {
                if (g < ng) {
#pragma unroll
                    for (int u = 0; u < GE; ++u) {
                        const int jj = min(g * GE + u, n - 1);
                        const int e = __shfl_sync(FULL, eid, jj);
                        cp_async16(sbase + (uint32_t)(g * GE + u) * 512u,
                                   x4 + (size_t)e * 32 + lane);
                    }
                }
                cp_commit();
            }

            for (int g = 0; g < ng; ++g) {
                cp_wait2();
                const int slot0 = (g % GS) * GE;
#pragma unroll
                for (int u = 0; u < GE; ++u) {
                    const int je = g * GE + u;
                    const int jj = min(je, n - 1);
                    const float m = (je < n) ? 1.f : 0.f;
                    const float r0 = __shfl_sync(FULL, rb0, jj);
                    const float r1 = __shfl_sync(FULL, rb1, jj);
                    const float r2 = __shfl_sync(FULL, rb2, jj);
                    const float r3 = __shfl_sync(FULL, rb3, jj);
                    const float r4 = __shfl_sync(FULL, rb4, jj);
                    const float r5 = __shfl_sync(FULL, rb5, jj);

                    const float4 xv = sx[wl][slot0 + u][lane];

                    float g0 = fmaf(r0, w[0].x, fmaf(r1, w[1].x, fmaf(r2, w[2].x,
                               fmaf(r3, w[3].x, fmaf(r4, w[4].x, r5 * w[5].x)))));
                    float g1 = fmaf(r0, w[0].y, fmaf(r1, w[1].y, fmaf(r2, w[2].y,
                               fmaf(r3, w[3].y, fmaf(r4, w[4].y, r5 * w[5].y)))));
                    float g2 = fmaf(r0, w[0].z, fmaf(r1, w[1].z, fmaf(r2, w[2].z,
                               fmaf(r3, w[3].z, fmaf(r4, w[4].z, r5 * w[5].z)))));
                    float g3 = fmaf(r0, w[0].w, fmaf(r1, w[1].w, fmaf(r2, w[2].w,
                               fmaf(r3, w[3].w, fmaf(r4, w[4].w, r5 * w[5].w)))));

                    a0 = fmaf(m * g0, xv.x, a0);
                    a1 = fmaf(m * g1, xv.y, a1);
                    a2 = fmaf(m * g2, xv.z, a2);
                    a3 = fmaf(m * g3, xv.w, a3);
                }
                const int gi = g + GS;
                if (gi < ng) {
#pragma unroll
                    for (int u = 0; u < GE; ++u) {
                        const int jj = min(gi * GE + u, n - 1);
                        const int e = __shfl_sync(FULL, eid, jj);
                        cp_async16(sbase + (uint32_t)((gi % GS) * GE + u) * 512u,
                                   x4 + (size_t)e * 32 + lane);
                    }
                }
                cp_commit();
            }
        }
        ((float4*)(g_h + (size_t)a * EMB))[lane] = make_float4(a0, a1, a2, a3);
    }
}

// ===================================================================
// Kernel 2: fused MLP head with conflict-free(er) epilogue.
//  - pairs 0..31 stored with column-keyed group rotation:
//      group(k, p0) at (p0 + 4*((k>>2)&7)) & 31
//    -> epilogue STS goes 32-way -> 8-way, 2x STS.128 per (q).
//  - pairs 32,33 live in a transposed side region hx[2][128]
//    (writes lane-strided -> 4-way; reads broadcast).
// ===================================================================
#define ROT(k)     ((((k) >> 2) & 7) << 2)
#define HS_BYTES   (EMB * PH * 8)          // 36864
#define HX_OFF     HS_BYTES                // 36864
#define HX_BYTES   (2 * EMB * 8)           // 2048
#define WS_OFF     (HX_OFF + HX_BYTES)     // 38912
#define WS_BYTES   (EMB * EMB * 4)         // 65536
#define WFS_OFF    (WS_OFF + WS_BYTES)     // 104448
#define WFS_BYTES  (EMB * NTP * 4)         // 8192
#define BS_OFF     (WFS_OFF + WFS_BYTES)   // 112640
#define BS_BYTES   (EMB * 4)               // 512
#define SMEM_TOTAL (BS_OFF + BS_BYTES)     // 113152  (x2 = 226304/SM)

__global__ __launch_bounds__(256, 2)
void mlp_kernel(const float* __restrict__ dW, const float* __restrict__ dB,
                const float* __restrict__ Wf, float* __restrict__ out,
                int n_atoms) {
    extern __shared__ char smem[];
    u64*   hsu = (u64*)smem;                 // rotated [col][pair<32], pitch PH
    u64*   hxu = (u64*)(smem + HX_OFF);      // [pair-32][col] side region
    float* Ws  = (float*)(smem + WS_OFF);
    float* Wfs = (float*)(smem + WFS_OFF);
    float* bss = (float*)(smem + BS_OFF);

    const int t = threadIdx.x;
    const int lane = t & 31, wid = t >> 5;
    const int rowbase = blockIdx.x * MLP_ROWS;

    // ---- reset scratch for the NEXT graph replay (after gather read it)
    {
        const int i = blockIdx.x * 256 + t;
        if (i < n_atoms) g_cnt[i] = 0;
        if (i == 0) g_ticket = 0;
    }

    // ---- load h tile (coalesced global read, rotated transpose store) ----
    for (int idx = t; idx < MLP_ROWS * EMB; idx += 256) {
        const int rr = idx >> 7, cc = idx & 127;
        const int gr = rowbase + rr;
        const float v = (gr < n_atoms) ? g_h[(size_t)gr * EMB + cc] : 0.f;
        const int pr = rr >> 1, half = rr & 1;
        float* dst;
        if (pr < 32) {
            const int s = ((pr & ~3) + ROT(cc)) & 31;
            dst = (float*)(hsu + cc * PH + s + (pr & 3));
        } else {
            dst = (float*)(hxu + (pr - 32) * EMB + cc);
        }
        dst[half] = v;
    }
    if (t < EMB) {
#pragma unroll
        for (int c = 0; c < NT; ++c) Wfs[t * NTP + c] = Wf[t * NT + c];
    }

    const int j0 = lane * 4;                 // 4 output cols per lane
    const int p0 = wid * 4;                  // pair base (0..28)
    const bool has_x = (wid < 2);            // extra pair 32+wid
    const int xrow = wid;                    // hx row for this warp

    // ---- dense layers ----
    for (int li = 0; li < NDENSE; ++li) {
        const float* W = dW + (size_t)li * EMB * EMB;
        {
            const float4* Wg = (const float4*)W;
            float4* Wd = (float4*)Ws;
            for (int idx = t; idx < EMB * EMB / 4; idx += 256) Wd[idx] = Wg[idx];
        }
        if (t < EMB) bss[t] = dB[li * EMB + t];
        __syncthreads();

        u64 acc[4][4], accx[4];
#pragma unroll
        for (int p = 0; p < 4; ++p)
#pragma unroll
            for (int q = 0; q < 4; ++q) acc[p][q] = 0ull;
#pragma unroll
        for (int q = 0; q < 4; ++q) accx[q] = 0ull;

#pragma unroll 2
        for (int k = 0; k < EMB; ++k) {
            const float4 wv = *(const float4*)&Ws[k * EMB + j0];
            const u64 w0 = pack2(wv.x, wv.x);
            const u64 w1 = pack2(wv.y, wv.y);
            const u64 w2 = pack2(wv.z, wv.z);
            const u64 w3 = pack2(wv.w, wv.w);
            const int s = (p0 + ROT(k)) & 31;
            const uint4* hp = (const uint4*)(hsu + k * PH + s);
            uint4 hvv[2];
            hvv[0] = hp[0];
            hvv[1] = hp[1];
            const u64* hq = (const u64*)hvv;
#pragma unroll
            for (int p = 0; p < 4; ++p) {
                acc[p][0] = ffma2(hq[p], w0, acc[p][0]);
                acc[p][1] = ffma2(hq[p], w1, acc[p][1]);
                acc[p][2] = ffma2(hq[p], w2, acc[p][2]);
                acc[p][3] = ffma2(hq[p], w3, acc[p][3]);
            }
            if (has_x) {                     // warp-uniform branch
                const u64 hx = hxu[xrow * EMB + k];
                accx[0] = ffma2(hx, w0, accx[0]);
                accx[1] = ffma2(hx, w1, accx[1]);
                accx[2] = ffma2(hx, w2, accx[2]);
                accx[3] = ffma2(hx, w3, accx[3]);
            }
        }

        float b[4];
#pragma unroll
        for (int q = 0; q < 4; ++q) b[q] = bss[j0 + q];

        __syncthreads();   // all reads done -> safe to overwrite

#pragma unroll
        for (int q = 0; q < 4; ++q) {
            const int col = j0 + q;
            const int s = (p0 + ROT(col)) & 31;
            u64* dst = hsu + col * PH + s;
            uint4 v01, v23;
            ((u64*)&v01)[0] = silu2(acc[0][q], b[q]);
            ((u64*)&v01)[1] = silu2(acc[1][q], b[q]);
            ((u64*)&v23)[0] = silu2(acc[2][q], b[q]);
            ((u64*)&v23)[1] = silu2(acc[3][q], b[q]);
            *(uint4*)dst = v01;              // pairs p0,p0+1
            *(uint4*)(dst + 2) = v23;        // pairs p0+2,p0+3
        }
        if (has_x) {
#pragma unroll
            for (int q = 0; q < 4; ++q)
                hxu[xrow * EMB + (j0 + q)] = silu2(accx[q], b[q]);
        }
        __syncthreads();
    }

    // ---- final projection: [68,128] @ [128,12] -> out ----
    const int c = t & 15;
    const int grp = t >> 4;      // 0..15
    if (c < NT) {
#pragma unroll
        for (int i = 0; i < 3; ++i) {
            const int pr = grp + 16 * i;
            if (pr < MLP_PAIRS) {
                u64 acc = 0ull;
                if (pr < 32) {
                    const int g4 = pr & ~3, w4i = pr & 3;
#pragma unroll 4
                    for (int k = 0; k < EMB; ++k) {
                        const float wfv = Wfs[k * NTP + c];
                        const int s = (g4 + ROT(k)) & 31;
                        acc = ffma2(hsu[k * PH + s + w4i], pack2(wfv, wfv), acc);
                    }
                } else {
#pragma unroll 4
                    for (int k = 0; k < EMB; ++k) {
                        const float wfv = Wfs[k * NTP + c];
                        acc = ffma2(hxu[(pr - 32) * EMB + k], pack2(wfv, wfv), acc);
                    }
                }
                float lo, hi;
                unpack2(acc, lo, hi);
                const int r0 = rowbase + 2 * pr;
                if (r0 < n_atoms)     out[(size_t)r0 * NT + c]       = lo;
                if (r0 + 1 < n_atoms) out[(size_t)(r0 + 1) * NT + c] = hi;
            }
        }
    }
}

// ===================================================================
extern "C" void kernel_launch(void* const* d_in, const int* in_sizes, int n_in,
                              void* d_out, int out_size) {
    const float* x    = (const float*)d_in[0];
    const float* rbf  = (const float*)d_in[1];
    const void*  idnb =               d_in[2];
    const float* Wrbf = (const float*)d_in[4];
    const float* dW   = (const float*)d_in[5];
    const float* dB   = (const float*)d_in[6];
    const float* Wf   = (const float*)d_in[7];
    float* out = (float*)d_out;

    const int E = in_sizes[0] / EMB;
    const int n_atoms = out_size / NT;

    bucket_kernel<<<592, 256>>>(idnb, E, n_atoms);          // 0
    gather_kernel<<<592, 256>>>(x, rbf, Wrbf, n_atoms);     // 1

    cudaFuncSetAttribute(mlp_kernel, cudaFuncAttributeMaxDynamicSharedMemorySize,
                         SMEM_TOTAL);
    const int blocks = (n_atoms + MLP_ROWS - 1) / MLP_ROWS;
    mlp_kernel<<<blocks, 256, SMEM_TOTAL>>>(dW, dB, Wf, out, n_atoms);  // 2
}

// round 17
// speedup vs baseline: 1.3783x; 1.0207x over previous
#include <cuda_runtime.h>
#include <cstdint>

#define EMB      128
#define NRAD     6
#define NDENSE   3
#define NT       12      // num targets
#define NTP      16      // padded targets in smem
#define MAX_ATOMS 20480
#define BCAP     128     // bucket capacity per atom (P(overflow) ~ e^-41)

#define TILE_ROWS 68     // atoms per fused block (2 blocks/SM)
#define TILE_PAIRS 34
#define PH        36     // u64 pitch for h tile
#define ROT(k)    ((((k) >> 2) & 7) << 2)

// -------- persistent device scratch (no allocations allowed) --------
__device__ __align__(16) float g_h_unused[16];            // (g_h eliminated)
__device__ __align__(16) int   g_cnt[MAX_ATOMS];          // zero-init; self-reset in fused
__device__ __align__(16) int   g_edges[MAX_ATOMS * BCAP]; // padded buckets (10.5 MB)

typedef unsigned long long u64;

// -------- packed fp32x2 helpers --------
__device__ __forceinline__ u64 ffma2(u64 a, u64 b, u64 c) {
    u64 d;
    asm("fma.rn.f32x2 %0, %1, %2, %3;" : "=l"(d) : "l"(a), "l"(b), "l"(c));
    return d;
}
__device__ __forceinline__ u64 pack2(float x, float y) {
    u64 r;
    asm("mov.b64 %0, {%1, %2};" : "=l"(r) : "f"(x), "f"(y));
    return r;
}
__device__ __forceinline__ void unpack2(u64 v, float& x, float& y) {
    asm("mov.b64 {%0, %1}, %2;" : "=f"(x), "=f"(y) : "l"(v));
}
__device__ __forceinline__ float silu_f(float x) {
    return __fdividef(x, 1.0f + __expf(-x));
}
__device__ __forceinline__ u64 silu2(u64 v, float b) {
    float lo, hi;
    unpack2(v, lo, hi);
    lo = silu_f(lo + b);
    hi = silu_f(hi + b);
    return pack2(lo, hi);
}

// -------- cp.async helpers --------
__device__ __forceinline__ void cp_async16(uint32_t saddr, const void* gptr) {
    asm volatile("cp.async.cg.shared.global [%0], [%1], 16;"
                 :: "r"(saddr), "l"(gptr) : "memory");
}
__device__ __forceinline__ void cp_commit() {
    asm volatile("cp.async.commit_group;" ::: "memory");
}
__device__ __forceinline__ void cp_wait3() {
    asm volatile("cp.async.wait_group 3;" ::: "memory");
}
__device__ __forceinline__ void cp_wait0() {
    asm volatile("cp.async.wait_group 0;" ::: "memory");
}

// -------- inline int64/int32 detection (deterministic) --------
__device__ __forceinline__ bool detect_is64(const void* idnb, int E, int n_atoms,
                                            int* s_flag) {
    if (threadIdx.x < 32) {
        const long long* p = (const long long*)idnb;
        int n = E / 2;
        if (n > 512) n = 512;
        int bad = 0;
        for (int i = threadIdx.x; i < n; i += 32) {
            long long v = p[i];
            if (v < 0 || v >= (long long)n_atoms) bad = 1;
        }
        bad = __any_sync(0xffffffffu, bad) ? 1 : 0;
        if (threadIdx.x == 0) *s_flag = bad ? 0 : 1;
    }
    __syncthreads();
    return *s_flag != 0;
}

// ===================================================================
// Kernel 0: single-pass padded-bucket CSR, 4-way unrolled (frozen).
// ===================================================================
__global__ __launch_bounds__(256)
void bucket_kernel(const void* __restrict__ idnb, int E, int n_atoms) {
    __shared__ int s_flag;
    const bool is64 = detect_is64(idnb, E, n_atoms, &s_flag);
    const long long* i64 = (const long long*)idnb;
    const int* i32 = (const int*)idnb;

    const int tid = blockIdx.x * blockDim.x + threadIdx.x;
    const int gs  = gridDim.x * blockDim.x;

    int e = tid * 4;
    const int stride = gs * 4;
    for (; e + 3 < E; e += stride) {
        int idx[4];
#pragma unroll
        for (int u = 0; u < 4; ++u)
            idx[u] = is64 ? (int)i64[e + u] : i32[e + u];
        int pos[4];
#pragma unroll
        for (int u = 0; u < 4; ++u)
            pos[u] = atomicAdd(&g_cnt[idx[u]], 1);
#pragma unroll
        for (int u = 0; u < 4; ++u)
            if (pos[u] < BCAP)
                g_edges[((size_t)idx[u] << 7) + pos[u]] = e + u;
    }
    for (; e < E; ++e) {
        const int idx = is64 ? (int)i64[e] : i32[e];
        const int pos = atomicAdd(&g_cnt[idx], 1);
        if (pos < BCAP)
            g_edges[((size_t)idx << 7) + pos] = e;
    }
}

// ===================================================================
// Kernel 1: FUSED gather + MLP. One block = one 68-atom tile.
// Phase A: 8 warps gather the tile's atoms (cp.async, GS=4 deep,
//   staging reuses the W smem region), h written straight into the
//   rotated smem tile (no g_h round-trip). Each block resets its
//   own g_cnt entries after reading them (graph-replay safe).
// Phase B: the R16 MLP body (h already resident in smem).
// Cross-block overlap: one block's DRAM-bound phase A runs under
// the co-resident block's compute-bound phase B.
// ===================================================================
#define GSF 4            // pipeline stages (fused)
#define GEF 4            // edges per stage
#define HS_BYTES   (EMB * PH * 8)          // 36864
#define HX_OFF     HS_BYTES                // 36864
#define HX_BYTES   (2 * EMB * 8)           // 2048
#define WS_OFF     (HX_OFF + HX_BYTES)     // 38912 (phase A: staging; phase B: W)
#define WS_BYTES   (EMB * EMB * 4)         // 65536 = 8 warps * 16 slots * 512
#define WFS_OFF    (WS_OFF + WS_BYTES)     // 104448
#define WFS_BYTES  (EMB * NTP * 4)         // 8192
#define BS_OFF     (WFS_OFF + WFS_BYTES)   // 112640
#define BS_BYTES   (EMB * 4)               // 512
#define SMEM_TOTAL (BS_OFF + BS_BYTES)     // 113152  (x2 = 226304/SM)

__global__ __launch_bounds__(256, 2)
void fused_kernel(const float* __restrict__ x,
                  const float* __restrict__ rbf,
                  const float* __restrict__ Wrbf,
                  const float* __restrict__ dW,
                  const float* __restrict__ dB,
                  const float* __restrict__ Wf,
                  float* __restrict__ out,
                  int n_atoms) {
    extern __shared__ char smem[];
    u64*   hsu = (u64*)smem;                 // rotated [col][pair<32], pitch PH
    u64*   hxu = (u64*)(smem + HX_OFF);      // [pair-32][col] side region
    float* Ws  = (float*)(smem + WS_OFF);    // phase B weight tile
    char*  stg = smem + WS_OFF;              // phase A cp.async staging
    float* Wfs = (float*)(smem + WFS_OFF);
    float* bss = (float*)(smem + BS_OFF);

    const int t = threadIdx.x;
    const int lane = t & 31, wid = t >> 5;
    const int rowbase = blockIdx.x * TILE_ROWS;
    const unsigned FULL = 0xffffffffu;

    // ================= Phase A: gather tile into smem =================
    // zero the h tile (covers atoms beyond n_atoms / short tiles)
    {
        uint4 z = make_uint4(0, 0, 0, 0);
        uint4* hz = (uint4*)smem;
        for (int i = t; i < (HS_BYTES + HX_BYTES) / 16; i += 256) hz[i] = z;
    }
    if (t < EMB) {
#pragma unroll
        for (int c = 0; c < NT; ++c) Wfs[t * NTP + c] = Wf[t * NT + c];
    }
    __syncthreads();

    {
        const uint32_t sbase = (uint32_t)__cvta_generic_to_shared(
            stg + wid * (GSF * GEF * 512) + lane * 16);
        float4 w[NRAD];
        const float4* w4 = (const float4*)Wrbf;
#pragma unroll
        for (int r = 0; r < NRAD; ++r) w[r] = w4[r * 32 + lane];
        const float4* x4 = (const float4*)x;
        const int j0 = lane * 4;

        for (int r = wid; r < TILE_ROWS; r += 8) {
            const int a = rowbase + r;
            if (a >= n_atoms) break;

            const int cnt = min(__ldg(&g_cnt[a]), BCAP);
            const int* bucket = g_edges + ((size_t)a << 7);
            float a0 = 0.f, a1 = 0.f, a2 = 0.f, a3 = 0.f;

            for (int base = 0; base < cnt; base += 32) {
                const int n = min(32, cnt - base);
                const int eid = __ldg(&bucket[base + min(lane, n - 1)]);

                const float* rp = rbf + (size_t)eid * NRAD;
                const float rb0 = __ldcs(rp + 0), rb1 = __ldcs(rp + 1);
                const float rb2 = __ldcs(rp + 2), rb3 = __ldcs(rp + 3);
                const float rb4 = __ldcs(rp + 4), rb5 = __ldcs(rp + 5);

                const int ng = (n + 3) >> 2;

#pragma unroll
                for (int g = 0; g < GSF; ++g) {
                    if (g < ng) {
#pragma unroll
                        for (int u = 0; u < GEF; ++u) {
                            const int jj = min(g * GEF + u, n - 1);
                            const int e = __shfl_sync(FULL, eid, jj);
                            cp_async16(sbase + (uint32_t)(g * GEF + u) * 512u,
                                       x4 + (size_t)e * 32 + lane);
                        }
                    }
                    cp_commit();
                }

                for (int g = 0; g < ng; ++g) {
                    cp_wait3();
                    const int slot0 = (g % GSF) * GEF;
#pragma unroll
                    for (int u = 0; u < GEF; ++u) {
                        const int je = g * GEF + u;
                        const int jj = min(je, n - 1);
                        const float m = (je < n) ? 1.f : 0.f;
                        const float r0 = __shfl_sync(FULL, rb0, jj);
                        const float r1 = __shfl_sync(FULL, rb1, jj);
                        const float r2 = __shfl_sync(FULL, rb2, jj);
                        const float r3 = __shfl_sync(FULL, rb3, jj);
                        const float r4 = __shfl_sync(FULL, rb4, jj);
                        const float r5 = __shfl_sync(FULL, rb5, jj);

                        const float4 xv = *(const float4*)(
                            stg + wid * (GSF * GEF * 512)
                                + (slot0 + u) * 512 + lane * 16);

                        float g0 = fmaf(r0, w[0].x, fmaf(r1, w[1].x, fmaf(r2, w[2].x,
                                   fmaf(r3, w[3].x, fmaf(r4, w[4].x, r5 * w[5].x)))));
                        float g1 = fmaf(r0, w[0].y, fmaf(r1, w[1].y, fmaf(r2, w[2].y,
                                   fmaf(r3, w[3].y, fmaf(r4, w[4].y, r5 * w[5].y)))));
                        float g2 = fmaf(r0, w[0].z, fmaf(r1, w[1].z, fmaf(r2, w[2].z,
                                   fmaf(r3, w[3].z, fmaf(r4, w[4].z, r5 * w[5].z)))));
                        float g3 = fmaf(r0, w[0].w, fmaf(r1, w[1].w, fmaf(r2, w[2].w,
                                   fmaf(r3, w[3].w, fmaf(r4, w[4].w, r5 * w[5].w)))));

                        a0 = fmaf(m * g0, xv.x, a0);
                        a1 = fmaf(m * g1, xv.y, a1);
                        a2 = fmaf(m * g2, xv.z, a2);
                        a3 = fmaf(m * g3, xv.w, a3);
                    }
                    const int gi = g + GSF;
                    if (gi < ng) {
#pragma unroll
                        for (int u = 0; u < GEF; ++u) {
                            const int jj = min(gi * GEF + u, n - 1);
                            const int e = __shfl_sync(FULL, eid, jj);
                            cp_async16(sbase + (uint32_t)((gi % GSF) * GEF + u) * 512u,
                                       x4 + (size_t)e * 32 + lane);
                        }
                    }
                    cp_commit();
                }
            }

            // write h row into the rotated tile (pair pr, half)
            const int pr = r >> 1, half = r & 1;
            float av[4] = {a0, a1, a2, a3};
            if (pr < 32) {
#pragma unroll
                for (int q = 0; q < 4; ++q) {
                    const int col = j0 + q;
                    const int s = ((pr & ~3) + ROT(col)) & 31;
                    ((float*)(hsu + col * PH + s + (pr & 3)))[half] = av[q];
                }
            } else {
#pragma unroll
                for (int q = 0; q < 4; ++q)
                    ((float*)(hxu + (pr - 32) * EMB + (j0 + q)))[half] = av[q];
            }
            if (lane == 0) g_cnt[a] = 0;     // self-reset for next replay
        }
        cp_wait0();                          // drain before staging -> W reuse
    }
    __syncthreads();

    // ================= Phase B: MLP on the resident tile =================
    const int j0 = lane * 4;
    const int p0 = wid * 4;
    const bool has_x = (wid < 2);
    const int xrow = wid;

    for (int li = 0; li < NDENSE; ++li) {
        const float* W = dW + (size_t)li * EMB * EMB;
        {
            const float4* Wg = (const float4*)W;
            float4* Wd = (float4*)Ws;
            for (int idx = t; idx < EMB * EMB / 4; idx += 256) Wd[idx] = Wg[idx];
        }
        if (t < EMB) bss[t] = dB[li * EMB + t];
        __syncthreads();

        u64 acc[4][4], accx[4];
#pragma unroll
        for (int p = 0; p < 4; ++p)
#pragma unroll
            for (int q = 0; q < 4; ++q) acc[p][q] = 0ull;
#pragma unroll
        for (int q = 0; q < 4; ++q) accx[q] = 0ull;

#pragma unroll 2
        for (int k = 0; k < EMB; ++k) {
            const float4 wv = *(const float4*)&Ws[k * EMB + j0];
            const u64 w0 = pack2(wv.x, wv.x);
            const u64 w1 = pack2(wv.y, wv.y);
            const u64 w2 = pack2(wv.z, wv.z);
            const u64 w3 = pack2(wv.w, wv.w);
            const int s = (p0 + ROT(k)) & 31;
            const uint4* hp = (const uint4*)(hsu + k * PH + s);
            uint4 hvv[2];
            hvv[0] = hp[0];
            hvv[1] = hp[1];
            const u64* hq = (const u64*)hvv;
#pragma unroll
            for (int p = 0; p < 4; ++p) {
                acc[p][0] = ffma2(hq[p], w0, acc[p][0]);
                acc[p][1] = ffma2(hq[p], w1, acc[p][1]);
                acc[p][2] = ffma2(hq[p], w2, acc[p][2]);
                acc[p][3] = ffma2(hq[p], w3, acc[p][3]);
            }
            if (has_x) {
                const u64 hx = hxu[xrow * EMB + k];
                accx[0] = ffma2(hx, w0, accx[0]);
                accx[1] = ffma2(hx, w1, accx[1]);
                accx[2] = ffma2(hx, w2, accx[2]);
                accx[3] = ffma2(hx, w3, accx[3]);
            }
        }

        float b[4];
#pragma unroll
        for (int q = 0; q < 4; ++q) b[q] = bss[j0 + q];

        __syncthreads();

#pragma unroll
        for (int q = 0; q < 4; ++q) {
            const int col = j0 + q;
            const int s = (p0 + ROT(col)) & 31;
            u64* dst = hsu + col * PH + s;
            uint4 v01, v23;
            ((u64*)&v01)[0] = silu2(acc[0][q], b[q]);
            ((u64*)&v01)[1] = silu2(acc[1][q], b[q]);
            ((u64*)&v23)[0] = silu2(acc[2][q], b[q]);
            ((u64*)&v23)[1] = silu2(acc[3][q], b[q]);
            *(uint4*)dst = v01;
            *(uint4*)(dst + 2) = v23;
        }
        if (has_x) {
#pragma unroll
            for (int q = 0; q < 4; ++q)
                hxu[xrow * EMB + (j0 + q)] = silu2(accx[q], b[q]);
        }
        __syncthreads();
    }

    // ---- final projection: [68,128] @ [128,12] -> out ----
    const int c = t & 15;
    const int grp = t >> 4;
    if (c < NT) {
#pragma unroll
        for (int i = 0; i < 3; ++i) {
            const int pr = grp + 16 * i;
            if (pr < TILE_PAIRS) {
                u64 acc = 0ull;
                if (pr < 32) {
                    const int g4 = pr & ~3, w4i = pr & 3;
#pragma unroll 4
                    for (int k = 0; k < EMB; ++k) {
                        const float wfv = Wfs[k * NTP + c];
                        const int s = (g4 + ROT(k)) & 31;
                        acc = ffma2(hsu[k * PH + s + w4i], pack2(wfv, wfv), acc);
                    }
                } else {
#pragma unroll 4
                    for (int k = 0; k < EMB; ++k) {
                        const float wfv = Wfs[k * NTP + c];
                        acc = ffma2(hxu[(pr - 32) * EMB + k], pack2(wfv, wfv), acc);
                    }
                }
                float lo, hi;
                unpack2(acc, lo, hi);
                const int r0 = rowbase + 2 * pr;
                if (r0 < n_atoms)     out[(size_t)r0 * NT + c]       = lo;
                if (r0 + 1 < n_atoms) out[(size_t)(r0 + 1) * NT + c] = hi;
            }
        }
    }
}

// ===================================================================
extern "C" void kernel_launch(void* const* d_in, const int* in_sizes, int n_in,
                              void* d_out, int out_size) {
    const float* x    = (const float*)d_in[0];
    const float* rbf  = (const float*)d_in[1];
    const void*  idnb =               d_in[2];
    const float* Wrbf = (const float*)d_in[4];
    const float* dW   = (const float*)d_in[5];
    const float* dB   = (const float*)d_in[6];
    const float* Wf   = (const float*)d_in[7];
    float* out = (float*)d_out;

    const int E = in_sizes[0] / EMB;
    const int n_atoms = out_size / NT;

    bucket_kernel<<<592, 256>>>(idnb, E, n_atoms);          // 0

    cudaFuncSetAttribute(fused_kernel, cudaFuncAttributeMaxDynamicSharedMemorySize,
                         SMEM_TOTAL);
    const int blocks = (n_atoms + TILE_ROWS - 1) / TILE_ROWS;
    fused_kernel<<<blocks, 256, SMEM_TOTAL>>>(x, rbf, Wrbf, dW, dB, Wf,
                                              out, n_atoms);  // 1
}